// round 16
// baseline (speedup 1.0000x reference)
#include <cuda_runtime.h>

#define B   8
#define CI  32
#define CO  32
#define NY  128
#define NX  128
#define M1  4
#define M2  5

#define TWO_PI_F 6.283185307179586476925f

typedef unsigned long long ull;

__device__ __forceinline__ float2 cmul(float2 a, float2 b) {
    return make_float2(a.x*b.x - a.y*b.y, a.x*b.y + a.y*b.x);
}
__device__ __forceinline__ float2 cfma(float2 a, float2 b, float2 c) {
    c.x = fmaf(a.x, b.x, fmaf(-a.y, b.y, c.x));
    c.y = fmaf(a.x, b.y, fmaf( a.y, b.x, c.y));
    return c;
}
__device__ __forceinline__ ull pack2(float lo, float hi) {
    ull r; asm("mov.b64 %0, {%1, %2};" : "=l"(r) : "f"(lo), "f"(hi)); return r;
}
__device__ __forceinline__ float2 unpack2(ull v) {
    float2 f; asm("mov.b64 {%0, %1}, %2;" : "=f"(f.x), "=f"(f.y) : "l"(v)); return f;
}
__device__ __forceinline__ ull fma2(ull a, ull b, ull c) {
    ull d; asm("fma.rn.f32x2 %0, %1, %2, %3;" : "=l"(d) : "l"(a), "l"(b), "l"(c)); return d;
}
__device__ __forceinline__ ull swap2(ull a) {
    float2 f = unpack2(a);
    return pack2(f.y, f.x);
}
template<int INV>
__device__ __forceinline__ float2 twmul(float2 v, float2 w) {
    if (INV) return make_float2(v.x*w.x + v.y*w.y, v.y*w.x - v.x*w.y);
    return make_float2(v.x*w.x - v.y*w.y, v.x*w.y + v.y*w.x);
}
// ---- tf32 mma helpers ----
__device__ __forceinline__ unsigned f2tf(float f) {
    unsigned r; asm("cvt.rna.tf32.f32 %0, %1;" : "=r"(r) : "f"(f)); return r;
}
__device__ __forceinline__ void mma_tf32(float* c, const unsigned* a, const unsigned* b) {
    asm volatile("mma.sync.aligned.m16n8k8.row.col.f32.tf32.tf32.f32 "
        "{%0,%1,%2,%3},{%4,%5,%6,%7},{%8,%9},{%0,%1,%2,%3};"
        : "+f"(c[0]), "+f"(c[1]), "+f"(c[2]), "+f"(c[3])
        : "r"(a[0]), "r"(a[1]), "r"(a[2]), "r"(a[3]), "r"(b[0]), "r"(b[1]));
}

// ---------------- scratch ---------------------------------------------------
__device__ float2 g_tmp  [B*CI*NY*NX];
__device__ float2 g_alpha[B*CI*NY*NX];
__device__ float2 g_A1   [CI*CO*M1*NY];
__device__ float2 g_A2   [CI*CO*M2*NX];
__device__ float2 g_E1   [CI*CO*M1*NY];
__device__ float2 g_E2   [CI*CO*M2*NX];
__device__ float2 g_H    [CI*CO*NY*NX];
__device__ float2 g_S1   [B*CI*CO*M1*NX];
__device__ float2 g_res2 [B*CO*M1*M2];

__device__ __forceinline__ void make_tws(float2* tws, int t) {
    if (t < 64) {
        float sn, cs;
        sincospif(-(float)t / 64.f, &sn, &cs);
        tws[t] = make_float2(cs, sn);
    }
}

// ---------------- pole factors E1/E2 + A1/A2 (launch 0) ----------------------
__global__ void k_fac(const float* __restrict__ wp1_re, const float* __restrict__ wp1_im,
                      const float* __restrict__ wp2_re, const float* __restrict__ wp2_im,
                      const float* __restrict__ ty, const float* __restrict__ tx) {
    int blk = blockIdx.x;
    int o   = threadIdx.x;
    if (blk < CI*CO*M1) {
        int ikp = blk;
        float wr = wp1_re[ikp], wi = wp1_im[ikp];
        float d = ty[1] - ty[0];
        float invnd = 1.0f / ((float)NY * d);
        float k = (o < NY/2) ? (float)o : (float)(o - NY);
        float lam = TWO_PI_F * k * invnd;
        float a = -wr, b = lam - wi;
        float inv = 1.0f / (a*a + b*b);
        g_A1[ikp*NY + o] = make_float2(a*inv, -b*inv);
        float t = ty[o];
        float e = expf(wr * t);
        float sn, cs; sincosf(wi * t, &sn, &cs);
        g_E1[ikp*NY + o] = make_float2(e*cs, e*sn);
    } else {
        int ikq = blk - CI*CO*M1;
        float wr = wp2_re[ikq], wi = wp2_im[ikq];
        float d = tx[1] - tx[0];
        float invnd = 1.0f / ((float)NX * d);
        float k = (o < NX/2) ? (float)o : (float)(o - NX);
        float lam = TWO_PI_F * k * invnd;
        float a = -wr, b = lam - wi;
        float inv = 1.0f / (a*a + b*b);
        g_A2[ikq*NX + o] = make_float2(a*inv, -b*inv);
        float t = tx[o];
        float e = expf(wr * t);
        float sn, cs; sincosf(wi * t, &sn, &cs);
        g_E2[ikq*NX + o] = make_float2(e*cs, e*sn);
    }
}

// ---------------- 128-pt radix-2 DIT (row FFT) -------------------------------
template<int INV>
__device__ __forceinline__ void fft64th(float2* s, int tt, const float2* tws) {
    #pragma unroll
    for (int stage = 1; stage <= 7; stage++) {
        __syncthreads();
        int half = 1 << (stage - 1);
        int p  = tt & (half - 1);
        int i0 = ((tt >> (stage - 1)) << stage) + p;
        int i1 = i0 + half;
        float2 w = tws[p << (7 - stage)];
        float2 u = s[i0];
        float2 v = twmul<INV>(s[i1], w);
        s[i0] = make_float2(u.x + v.x, u.y + v.y);
        s[i1] = make_float2(u.x - v.x, u.y - v.y);
    }
}

// forward FFT of real rows (launch 1)
__global__ void k_fft_rows_f(const float* __restrict__ x) {
    __shared__ float2 s[2][NX];
    __shared__ float2 tws[64];
    int t = threadIdx.x, r = t >> 6, tt = t & 63;
    make_tws(tws, t);
    size_t row = (size_t)blockIdx.x * 2 + r;
    const float* xr = x + row * NX;
    s[r][tt]      = make_float2(xr[__brev(tt)      >> 25], 0.f);
    s[r][tt + 64] = make_float2(xr[__brev(tt + 64) >> 25], 0.f);
    fft64th<0>(s[r], tt, tws);
    float2* o = g_tmp + row * NX;
    o[tt] = s[r][tt]; o[tt + 64] = s[r][tt + 64];
}

// ---------------- fused-pair (radix-4 style) column FFT ----------------------
template<int INV>
__device__ __forceinline__ void fft_col4(float2 (*tile)[17], int tg, int tx, const float2* tws) {
    #pragma unroll
    for (int s = 1; s <= 5; s += 2) {
        __syncthreads();
        int h = 1 << (s - 1);
        #pragma unroll
        for (int m = 0; m < 4; m++) {
            int j = tg + 8 * m;
            int p = j & (h - 1);
            int base = ((j >> (s - 1)) << (s + 1)) + p;
            float2 w1  = tws[p << (7 - s)];
            float2 w2  = tws[p << (6 - s)];
            float2 w2b = tws[(p + h) << (6 - s)];
            float2 a = tile[base][tx],       bb = tile[base + h][tx];
            float2 c = tile[base + 2*h][tx], dd = tile[base + 3*h][tx];
            float2 vb = twmul<INV>(bb, w1);
            float2 vd = twmul<INV>(dd, w1);
            float2 a1 = make_float2(a.x + vb.x, a.y + vb.y);
            float2 b1 = make_float2(a.x - vb.x, a.y - vb.y);
            float2 c1 = make_float2(c.x + vd.x, c.y + vd.y);
            float2 d1 = make_float2(c.x - vd.x, c.y - vd.y);
            float2 vc = twmul<INV>(c1, w2);
            float2 ve = twmul<INV>(d1, w2b);
            tile[base][tx]       = make_float2(a1.x + vc.x, a1.y + vc.y);
            tile[base + 2*h][tx] = make_float2(a1.x - vc.x, a1.y - vc.y);
            tile[base + h][tx]   = make_float2(b1.x + ve.x, b1.y + ve.y);
            tile[base + 3*h][tx] = make_float2(b1.x - ve.x, b1.y - ve.y);
        }
    }
    __syncthreads();
    #pragma unroll
    for (int m = 0; m < 8; m++) {
        int j = tg + 8 * m;
        float2 w = tws[j];
        float2 u = tile[j][tx];
        float2 v = twmul<INV>(tile[j + 64][tx], w);
        tile[j][tx]      = make_float2(u.x + v.x, u.y + v.y);
        tile[j + 64][tx] = make_float2(u.x - v.x, u.y - v.y);
    }
}

// forward columns (launch 2): g_tmp -> g_alpha
__global__ void k_fft_cols_f() {
    __shared__ float2 tile[NY][17];
    __shared__ float2 tws[64];
    int t = threadIdx.x;
    make_tws(tws, t);
    int blk = blockIdx.x;
    int xt = blk & 7, img = blk >> 3;
    int x0 = xt * 16;
    int tg = t >> 4, tx = t & 15;
    const float2* base = g_tmp + (size_t)img * NY * NX + x0;
    #pragma unroll
    for (int c = 0; c < 16; c++) {
        int y = c * 8 + tg;
        tile[__brev(y) >> 25][tx] = base[(size_t)y * NX + tx];
    }
    fft_col4<0>(tile, tg, tx, tws);
    __syncthreads();
    float2* ob = g_alpha + (size_t)img * NY * NX + x0;
    #pragma unroll
    for (int c = 0; c < 16; c++) {
        int y = c * 8 + tg;
        ob[(size_t)y * NX + tx] = tile[y][tx];
    }
}

// ---------------- S1 via tf32 tensor cores, 3xTF32 split (launch 3) ----------
// S1[bi][kp][x] = sum_o A1[i][kp][o] * alpha[bi][o][x]   (complex)
// 4 real GEMM products, each as 3 mma terms (hi*hi + lo*hi + hi*lo).
// Block = (bi, x-half of 64). smem: B planes (alpha) 128KB + A chunk planes 96KB.
// Fragment-order smem staging -> 1 LDS.128 per A frag, 1 LDS.64 per B frag.
#define S1M_SMEM (57344 * 4)
extern __shared__ float2 dynsm[];
__global__ void __launch_bounds__(256, 1) k_S1() {
    unsigned* sm = (unsigned*)dynsm;
    unsigned* Bp = sm;                 // 4 planes x 8192: Brh, Brl, Bih, Bil
    unsigned* Ap = sm + 4*8192;        // 6 planes x 4096: Arh, Arl, Aih, Ail, nAih, nAil
    int blk = blockIdx.x;
    int xh = blk & 1;
    int bi = blk >> 1;
    int i  = bi & 31;
    int x0 = xh * 64;
    int t  = threadIdx.x;
    // stage B = alpha[bi][o=0..127][x0..x0+63], split hi/lo, fragment order
    const float2* A = g_alpha + (size_t)bi * NY * NX + x0;
    for (int e = t; e < 128*64; e += 256) {
        int o = e >> 6, x = e & 63;
        float2 v = A[(size_t)o * NX + x];
        unsigned rh = f2tf(v.x); float rlo = v.x - __uint_as_float(rh);
        unsigned ih = f2tf(v.y); float ilo = v.y - __uint_as_float(ih);
        int nt = x >> 3, n = x & 7, ks = o >> 3, k = o & 7;
        int idx = ((nt*16 + ks)*32 + (n*4 + (k & 3)))*2 + (k >> 2);
        Bp[idx]         = rh;
        Bp[8192  + idx] = f2tf(rlo);
        Bp[16384 + idx] = ih;
        Bp[24576 + idx] = f2tf(ilo);
    }
    int w = t >> 5, l = t & 31;
    int mt = w & 1;                    // warp m-tile (16 rows) within 32-kp chunk
    int nb = (w >> 1) * 2;             // warp's first n8-tile (2 per warp)
    #pragma unroll 1
    for (int c = 0; c < 4; c++) {
        int kp0 = c * 32;
        __syncthreads();
        // stage A chunk = A1[i][kp0..kp0+31][o], split hi/lo (+negated Ai), frag order
        for (int e = t; e < 32*128; e += 256) {
            int m = e >> 7, o = e & 127;
            float2 v = g_A1[((size_t)i*CO*M1 + kp0 + m) * NY + o];
            unsigned rh = f2tf(v.x); float rlo = v.x - __uint_as_float(rh);
            unsigned ih = f2tf(v.y); float ilo = v.y - __uint_as_float(ih);
            unsigned rl = f2tf(rlo), il = f2tf(ilo);
            int mtile = m >> 4, mm = m & 15, ks = o >> 3, k = o & 7;
            int lane = (mm & 7)*4 + (k & 3);
            int reg  = (mm >> 3) + 2*(k >> 2);
            int idx = ((mtile*16 + ks)*32 + lane)*4 + reg;
            Ap[idx]         = rh;
            Ap[4096  + idx] = rl;
            Ap[8192  + idx] = ih;
            Ap[12288 + idx] = il;
            Ap[16384 + idx] = ih ^ 0x80000000u;
            Ap[20480 + idx] = il ^ 0x80000000u;
        }
        __syncthreads();
        float cre[2][4] = {{0.f,0.f,0.f,0.f},{0.f,0.f,0.f,0.f}};
        float cim[2][4] = {{0.f,0.f,0.f,0.f},{0.f,0.f,0.f,0.f}};
        #pragma unroll 2
        for (int ks = 0; ks < 16; ks++) {
            unsigned arh[4], arl[4], aih[4], ail[4], nih[4], nil[4];
            int abase = ((mt*16 + ks)*32 + l)*4;
            *(uint4*)arh = *(const uint4*)&Ap[abase];
            *(uint4*)arl = *(const uint4*)&Ap[4096  + abase];
            *(uint4*)aih = *(const uint4*)&Ap[8192  + abase];
            *(uint4*)ail = *(const uint4*)&Ap[12288 + abase];
            *(uint4*)nih = *(const uint4*)&Ap[16384 + abase];
            *(uint4*)nil = *(const uint4*)&Ap[20480 + abase];
            #pragma unroll
            for (int j = 0; j < 2; j++) {
                int bbase = (((nb + j)*16 + ks)*32 + l)*2;
                unsigned brh[2], brl[2], bih[2], bil[2];
                *(uint2*)brh = *(const uint2*)&Bp[bbase];
                *(uint2*)brl = *(const uint2*)&Bp[8192  + bbase];
                *(uint2*)bih = *(const uint2*)&Bp[16384 + bbase];
                *(uint2*)bil = *(const uint2*)&Bp[24576 + bbase];
                mma_tf32(cre[j], arh, brh);
                mma_tf32(cre[j], arl, brh);
                mma_tf32(cre[j], arh, brl);
                mma_tf32(cre[j], nih, bih);
                mma_tf32(cre[j], nil, bih);
                mma_tf32(cre[j], nih, bil);
                mma_tf32(cim[j], arh, bih);
                mma_tf32(cim[j], arl, bih);
                mma_tf32(cim[j], arh, bil);
                mma_tf32(cim[j], aih, brh);
                mma_tf32(cim[j], ail, brh);
                mma_tf32(cim[j], aih, brl);
            }
        }
        int row0 = kp0 + mt*16 + (l >> 2);
        #pragma unroll
        for (int j = 0; j < 2; j++) {
            int col = x0 + (nb + j)*8 + (l & 3)*2;
            float4 v0 = make_float4(cre[j][0], cim[j][0], cre[j][1], cim[j][1]);
            float4 v1 = make_float4(cre[j][2], cim[j][2], cre[j][3], cim[j][3]);
            *(float4*)(g_S1 + ((size_t)bi*CO*M1 + row0) * NX + col)     = v0;
            *(float4*)(g_S1 + ((size_t)bi*CO*M1 + row0 + 8) * NX + col) = v1;
        }
    }
}

// ---------------- Hsum with inline A1/A2 (launch 4) --------------------------
__global__ void k_hsum(const float* __restrict__ wp1_re, const float* __restrict__ wp1_im,
                       const float* __restrict__ wp2_re, const float* __restrict__ wp2_im,
                       const float* __restrict__ ty, const float* __restrict__ tx,
                       const float* __restrict__ wr_re, const float* __restrict__ wr_im) {
    int ik = blockIdx.x;
    int t  = threadIdx.x;
    __shared__ float2 wrS[M1*M2];
    __shared__ float2 A1S[M1][NY];
    __shared__ float2 U[M2][NY];
    if (t < M1*M2) wrS[t] = make_float2(wr_re[ik*M1*M2 + t], wr_im[ik*M1*M2 + t]);
    float kf = (t < NY/2) ? (float)t : (float)(t - NY);
    {
        float d = ty[1] - ty[0];
        float invnd = 1.0f / ((float)NY * d);
        float lam = TWO_PI_F * kf * invnd;
        #pragma unroll
        for (int p = 0; p < M1; p++) {
            float wr = wp1_re[ik*M1 + p], wi = wp1_im[ik*M1 + p];
            float a = -wr, b = lam - wi;
            float inv = 1.0f / (a*a + b*b);
            A1S[p][t] = make_float2(a*inv, -b*inv);
        }
    }
    float2 a2[M2];
    {
        float d = tx[1] - tx[0];
        float invnd = 1.0f / ((float)NX * d);
        float lam = TWO_PI_F * kf * invnd;
        #pragma unroll
        for (int q = 0; q < M2; q++) {
            float wr = wp2_re[ik*M2 + q], wi = wp2_im[ik*M2 + q];
            float a = -wr, b = lam - wi;
            float inv = 1.0f / (a*a + b*b);
            a2[q] = make_float2(a*inv, -b*inv);
        }
    }
    __syncthreads();
    #pragma unroll
    for (int q = 0; q < M2; q++) {
        float2 acc = make_float2(0.f, 0.f);
        #pragma unroll
        for (int p = 0; p < M1; p++) acc = cfma(wrS[p*M2 + q], A1S[p][t], acc);
        U[q][t] = acc;
    }
    __syncthreads();
    float2* H = g_H + (size_t)ik * NY * NX;
    for (int o = 0; o < NY; o++) {
        float2 acc = make_float2(0.f, 0.f);
        #pragma unroll
        for (int q = 0; q < M2; q++) acc = cfma(U[q][o], a2[q], acc);
        __stcs(&H[o*NX + t], acc);
    }
}

// ---------------- res2 (launch 5) --------------------------------------------
__global__ void k_res2(const float* __restrict__ wr_re, const float* __restrict__ wr_im) {
    int bk = blockIdx.x;
    int b = bk >> 5, k = bk & 31;
    int t = threadIdx.x;
    __shared__ float2 wrS[CI][M1*M2];
    for (int idx = t; idx < CI*M1*M2; idx += 128) {
        int i = idx / (M1*M2), pq = idx % (M1*M2);
        wrS[i][pq] = make_float2(wr_re[(i*CO + k)*M1*M2 + pq], wr_im[(i*CO + k)*M1*M2 + pq]);
    }
    __syncthreads();
    float2 acc[M1*M2];
    #pragma unroll
    for (int j = 0; j < M1*M2; j++) acc[j] = make_float2(0.f, 0.f);
    for (int i = 0; i < CI; i++) {
        float2 s1[M1], a2[M2];
        #pragma unroll
        for (int p = 0; p < M1; p++)
            s1[p] = g_S1[((size_t)(b*CI + i)*CO*M1 + k*M1 + p)*NX + t];
        #pragma unroll
        for (int q = 0; q < M2; q++)
            a2[q] = g_A2[((size_t)(i*CO + k)*M2 + q)*NX + t];
        #pragma unroll
        for (int p = 0; p < M1; p++)
            #pragma unroll
            for (int q = 0; q < M2; q++) {
                float2 wa = cmul(wrS[i][p*M2 + q], s1[p]);
                acc[p*M2 + q] = cfma(wa, a2[q], acc[p*M2 + q]);
            }
    }
    #pragma unroll
    for (int j = 0; j < M1*M2; j++)
        #pragma unroll
        for (int off = 16; off; off >>= 1) {
            acc[j].x += __shfl_down_sync(0xffffffffu, acc[j].x, off);
            acc[j].y += __shfl_down_sync(0xffffffffu, acc[j].y, off);
        }
    __shared__ float2 red[4][M1*M2];
    int w = t >> 5, lane = t & 31;
    if (lane == 0) {
        #pragma unroll
        for (int j = 0; j < M1*M2; j++) red[w][j] = acc[j];
    }
    __syncthreads();
    if (t < M1*M2) {
        float2 s = red[0][t];
        #pragma unroll
        for (int w2 = 1; w2 < 4; w2++) { s.x += red[w2][t].x; s.y += red[w2][t].y; }
        g_res2[bk*M1*M2 + t] = s;
    }
}

// ---------------- res1 + inverse row FFT (fused pairs), k-tile 2 (launch 6) --
__global__ void __launch_bounds__(128, 5) k_res1f() {
    __shared__ float2 rows[16][129];
    __shared__ float2 tws[64];
    int o  = blockIdx.x & 127;
    int k0 = (blockIdx.x >> 7) * 2;
    int x  = threadIdx.x;
    make_tws(tws, x);
    const ull* alphaU = (const ull*)g_alpha;
    ull acc[2][B];
    #pragma unroll
    for (int kk = 0; kk < 2; kk++)
        #pragma unroll
        for (int b = 0; b < B; b++) acc[kk][b] = pack2(0.f, 0.f);

    for (int i = 0; i < CI; i++) {
        float2 hc[2];
        #pragma unroll
        for (int kk = 0; kk < 2; kk++)
            hc[kk] = __ldcs(&g_H[((size_t)(i*CO + k0 + kk) * NY + o) * NX + x]);
        ull ac[8];
        #pragma unroll
        for (int b = 0; b < B; b++)
            ac[b] = alphaU[((size_t)(b*CI + i) * NY + o) * NX + x];
        ull hxx[2], hpm[2];
        #pragma unroll
        for (int kk = 0; kk < 2; kk++) {
            hxx[kk] = pack2(hc[kk].x,  hc[kk].x);
            hpm[kk] = pack2(-hc[kk].y, hc[kk].y);
        }
        #pragma unroll
        for (int b = 0; b < B; b++) {
            ull au = ac[b];
            ull as = swap2(au);
            #pragma unroll
            for (int kk = 0; kk < 2; kk++) {
                acc[kk][b] = fma2(au, hxx[kk], acc[kk][b]);
                acc[kk][b] = fma2(as, hpm[kk], acc[kk][b]);
            }
        }
    }
    int xr = __brev(x) >> 25;
    #pragma unroll
    for (int kk = 0; kk < 2; kk++)
        #pragma unroll
        for (int b = 0; b < B; b++)
            rows[kk*8 + b][xr] = unpack2(acc[kk][b]);
    __syncthreads();
    #pragma unroll
    for (int s = 1; s <= 5; s += 2) {
        int h = 1 << (s - 1);
        #pragma unroll
        for (int m = 0; m < 4; m++) {
            int l = x + 128 * m;
            int r = l >> 5, j = l & 31;
            int p = j & (h - 1);
            int base = ((j >> (s - 1)) << (s + 1)) + p;
            float2 w1  = tws[p << (7 - s)];
            float2 w2  = tws[p << (6 - s)];
            float2 w2b = tws[(p + h) << (6 - s)];
            float2 a = rows[r][base],       bb = rows[r][base + h];
            float2 c = rows[r][base + 2*h], dd = rows[r][base + 3*h];
            float2 vb = twmul<1>(bb, w1);
            float2 vd = twmul<1>(dd, w1);
            float2 a1 = make_float2(a.x + vb.x, a.y + vb.y);
            float2 b1 = make_float2(a.x - vb.x, a.y - vb.y);
            float2 c1 = make_float2(c.x + vd.x, c.y + vd.y);
            float2 d1 = make_float2(c.x - vd.x, c.y - vd.y);
            float2 vc = twmul<1>(c1, w2);
            float2 ve = twmul<1>(d1, w2b);
            rows[r][base]       = make_float2(a1.x + vc.x, a1.y + vc.y);
            rows[r][base + 2*h] = make_float2(a1.x - vc.x, a1.y - vc.y);
            rows[r][base + h]   = make_float2(b1.x + ve.x, b1.y + ve.y);
            rows[r][base + 3*h] = make_float2(b1.x - ve.x, b1.y - ve.y);
        }
        __syncthreads();
    }
    #pragma unroll
    for (int m = 0; m < 8; m++) {
        int l = x + 128 * m;
        int r = l >> 6, j = l & 63;
        float2 w = tws[j];
        float2 u = rows[r][j];
        float2 v = twmul<1>(rows[r][j + 64], w);
        rows[r][j]      = make_float2(u.x + v.x, u.y + v.y);
        rows[r][j + 64] = make_float2(u.x - v.x, u.y - v.y);
    }
    __syncthreads();
    #pragma unroll
    for (int kk = 0; kk < 2; kk++)
        #pragma unroll
        for (int b = 0; b < B; b++)
            g_tmp[(((size_t)(b*CO + k0 + kk)) * NY + o) * NX + x] = rows[kk*8 + b][x];
}

// ---------------- inverse columns, fused pairs (launch 7) --------------------
__global__ void k_ifft_cols_r(float* __restrict__ out) {
    __shared__ float2 tile[NY][17];
    __shared__ float2 tws[64];
    int t = threadIdx.x;
    make_tws(tws, t);
    int blk = blockIdx.x;
    int xt = blk & 7, img = blk >> 3;
    int x0 = xt * 16;
    int tg = t >> 4, tx = t & 15;
    const float2* base = g_tmp + (size_t)img * NY * NX + x0;
    #pragma unroll
    for (int c = 0; c < 16; c++) {
        int y = c * 8 + tg;
        tile[__brev(y) >> 25][tx] = base[(size_t)y * NX + tx];
    }
    fft_col4<1>(tile, tg, tx, tws);
    __syncthreads();
    const float INV = 1.0f / (float)(NY * NX);
    float* ob = out + (size_t)img * NY * NX + x0;
    #pragma unroll
    for (int c = 0; c < 16; c++) {
        int y = c * 8 + tg;
        ob[(size_t)y * NX + tx] = tile[y][tx].x * INV;
    }
}

// ---------------- x2 with fused G (launch 8) ---------------------------------
#define X2_E1   (128*64)
#define X2_R2   (CI*M1*M2)
#define X2_GS   (16*66)
#define X2_ES   (16*129)
#define X2_SMEM ((X2_E1 + X2_R2 + X2_GS + X2_ES) * sizeof(float2))
__global__ void __launch_bounds__(256) k_x2(float* __restrict__ out) {
    float2* e1S = dynsm;
    float2* r2S = e1S + X2_E1;
    float2* Gs  = r2S + X2_R2;
    float2* Es  = Gs + X2_GS;
    int blk = blockIdx.x;
    int zh  = blk & 1;
    int bk  = blk >> 1;
    int b = bk >> 5, k = bk & 31;
    int z0 = zh * 64;
    int t = threadIdx.x;
    int u = t >> 5, v = t & 31;
    for (int l = t; l < X2_E1; l += 256) {
        int cp = l >> 6, zz = l & 63;
        e1S[l] = g_E1[(((cp >> 2)*CO + k)*M1 + (cp & 3))*NY + z0 + zz];
    }
    for (int l = t; l < X2_R2; l += 256)
        r2S[l] = g_res2[(b*CO + (l/20))*20 + (l%20)];
    ull acc[8][4];
    #pragma unroll
    for (int j = 0; j < 8; j++)
        #pragma unroll
        for (int m = 0; m < 4; m++) acc[j][m] = pack2(0.f, 0.f);
    for (int k0 = 0; k0 < CI*M2; k0 += 16) {
        __syncthreads();
        for (int l = t; l < 16*64; l += 256) {
            int r = l >> 6, zz = l & 63;
            int cq = k0 + r; int c = cq / M2, q = cq % M2;
            float2 g = make_float2(0.f, 0.f);
            #pragma unroll
            for (int p = 0; p < M1; p++)
                g = cfma(r2S[c*20 + p*M2 + q], e1S[(c*4 + p)*64 + zz], g);
            Gs[r*66 + zz] = g;
        }
        for (int l = t; l < 16*128; l += 256) {
            int r = l >> 7, xx = l & 127;
            int cq = k0 + r; int c = cq / M2, q = cq % M2;
            Es[r*129 + xx] = g_E2[((size_t)(c*CO + k)*M2 + q)*NX + xx];
        }
        __syncthreads();
        #pragma unroll
        for (int kk = 0; kk < 16; kk++) {
            ulonglong2 gp[4];
            const ulonglong2* gq = (const ulonglong2*)&Gs[kk*66 + u*8];
            #pragma unroll
            for (int jp = 0; jp < 4; jp++) gp[jp] = gq[jp];
            #pragma unroll
            for (int m = 0; m < 4; m++) {
                ull e = *(const ull*)&Es[kk*129 + v + 32*m];
                #pragma unroll
                for (int jp = 0; jp < 4; jp++) {
                    acc[2*jp  ][m] = fma2(gp[jp].x, e, acc[2*jp  ][m]);
                    acc[2*jp+1][m] = fma2(gp[jp].y, e, acc[2*jp+1][m]);
                }
            }
        }
    }
    const float INV = 1.0f / (float)(NY * NX);
    float* ob = out + (size_t)(b*CO + k) * NY * NX;
    #pragma unroll
    for (int j = 0; j < 8; j++) {
        int z = z0 + u*8 + j;
        #pragma unroll
        for (int m = 0; m < 4; m++) {
            float2 r = unpack2(acc[j][m]);
            ob[(size_t)z * NX + v + 32*m] += (r.x - r.y) * INV;
        }
    }
}

// ---------------------------------------------------------------------------
extern "C" void kernel_launch(void* const* d_in, const int* in_sizes, int n_in,
                              void* d_out, int out_size) {
    const float* x      = (const float*)d_in[0];
    const float* wp1_re = (const float*)d_in[1];
    const float* wp1_im = (const float*)d_in[2];
    const float* wp2_re = (const float*)d_in[3];
    const float* wp2_im = (const float*)d_in[4];
    const float* wr_re  = (const float*)d_in[5];
    const float* wr_im  = (const float*)d_in[6];
    const float* ty     = (const float*)d_in[7];
    const float* tx     = (const float*)d_in[8];
    float* out = (float*)d_out;

    cudaFuncSetAttribute(k_S1, cudaFuncAttributeMaxDynamicSharedMemorySize, S1M_SMEM);
    cudaFuncSetAttribute(k_x2, cudaFuncAttributeMaxDynamicSharedMemorySize, (int)X2_SMEM);

    k_fac         <<<CI*CO*(M1+M2), 128>>>(wp1_re, wp1_im, wp2_re, wp2_im, ty, tx);       // 0
    k_fft_rows_f  <<<B*CI*NY/2, 128>>>(x);                                                // 1
    k_fft_cols_f  <<<B*CI*8, 128>>>();                                                    // 2
    k_S1          <<<B*CI*2, 256, S1M_SMEM>>>();                                          // 3 (profiled)
    k_hsum        <<<CI*CO, 128>>>(wp1_re, wp1_im, wp2_re, wp2_im, ty, tx, wr_re, wr_im); // 4
    k_res2        <<<B*CO, 128>>>(wr_re, wr_im);                                          // 5
    k_res1f       <<<16*NY, 128>>>();                                                     // 6
    k_ifft_cols_r <<<B*CO*8, 128>>>(out);                                                 // 7
    k_x2          <<<B*CO*2, 256, X2_SMEM>>>(out);                                        // 8
}

// round 17
// speedup vs baseline: 1.0623x; 1.0623x over previous
#include <cuda_runtime.h>

#define B   8
#define CI  32
#define CO  32
#define NY  128
#define NX  128
#define M1  4
#define M2  5

#define TWO_PI_F 6.283185307179586476925f

typedef unsigned long long ull;

__device__ __forceinline__ float2 cmul(float2 a, float2 b) {
    return make_float2(a.x*b.x - a.y*b.y, a.x*b.y + a.y*b.x);
}
__device__ __forceinline__ float2 cfma(float2 a, float2 b, float2 c) {
    c.x = fmaf(a.x, b.x, fmaf(-a.y, b.y, c.x));
    c.y = fmaf(a.x, b.y, fmaf( a.y, b.x, c.y));
    return c;
}
__device__ __forceinline__ ull pack2(float lo, float hi) {
    ull r; asm("mov.b64 %0, {%1, %2};" : "=l"(r) : "f"(lo), "f"(hi)); return r;
}
__device__ __forceinline__ float2 unpack2(ull v) {
    float2 f; asm("mov.b64 {%0, %1}, %2;" : "=f"(f.x), "=f"(f.y) : "l"(v)); return f;
}
__device__ __forceinline__ ull fma2(ull a, ull b, ull c) {
    ull d; asm("fma.rn.f32x2 %0, %1, %2, %3;" : "=l"(d) : "l"(a), "l"(b), "l"(c)); return d;
}
__device__ __forceinline__ ull swap2(ull a) {
    float2 f = unpack2(a);
    return pack2(f.y, f.x);
}
template<int INV>
__device__ __forceinline__ float2 twmul(float2 v, float2 w) {
    if (INV) return make_float2(v.x*w.x + v.y*w.y, v.y*w.x - v.x*w.y);
    return make_float2(v.x*w.x - v.y*w.y, v.x*w.y + v.y*w.x);
}
// ---- tf32 mma helpers ----
__device__ __forceinline__ unsigned f2tf(float f) {
    unsigned r; asm("cvt.rna.tf32.f32 %0, %1;" : "=r"(r) : "f"(f)); return r;
}
__device__ __forceinline__ void mma_tf32(float* c, const unsigned* a, const unsigned* b) {
    asm volatile("mma.sync.aligned.m16n8k8.row.col.f32.tf32.tf32.f32 "
        "{%0,%1,%2,%3},{%4,%5,%6,%7},{%8,%9},{%0,%1,%2,%3};"
        : "+f"(c[0]), "+f"(c[1]), "+f"(c[2]), "+f"(c[3])
        : "r"(a[0]), "r"(a[1]), "r"(a[2]), "r"(a[3]), "r"(b[0]), "r"(b[1]));
}

// ---------------- scratch ---------------------------------------------------
#define A1F_P (32*16384)                 // per-plane size: 32 i x 128 kp x 128 o
__device__ float2 g_tmp  [B*CI*NY*NX];
__device__ float2 g_alpha[B*CI*NY*NX];
__device__ unsigned g_A1f[6*A1F_P];      // tf32 frag planes: rh, rl, ih, il, nih, nil
__device__ float2 g_A2   [CI*CO*M2*NX];
__device__ float2 g_E1   [CI*CO*M1*NY];
__device__ float2 g_E2   [CI*CO*M2*NX];
__device__ float2 g_H    [CI*CO*NY*NX];
__device__ float2 g_S1   [B*CI*CO*M1*NX];
__device__ float2 g_res2 [B*CO*M1*M2];

__device__ __forceinline__ void make_tws(float2* tws, int t) {
    if (t < 64) {
        float sn, cs;
        sincospif(-(float)t / 64.f, &sn, &cs);
        tws[t] = make_float2(cs, sn);
    }
}

// ---------------- pole factors: E1/E2, A2, A1 frag planes (launch 0) ---------
__global__ void k_fac(const float* __restrict__ wp1_re, const float* __restrict__ wp1_im,
                      const float* __restrict__ wp2_re, const float* __restrict__ wp2_im,
                      const float* __restrict__ ty, const float* __restrict__ tx) {
    int blk = blockIdx.x;
    int o   = threadIdx.x;
    if (blk < CI*CO*M1) {
        int ikp = blk;
        int i = ikp >> 7, kp = ikp & 127;
        float wr = wp1_re[ikp], wi = wp1_im[ikp];
        float d = ty[1] - ty[0];
        float invnd = 1.0f / ((float)NY * d);
        float k = (o < NY/2) ? (float)o : (float)(o - NY);
        float lam = TWO_PI_F * k * invnd;
        float a = -wr, b = lam - wi;
        float inv = 1.0f / (a*a + b*b);
        float vre = a*inv, vim = -b*inv;
        // tf32 split, fragment-order store
        unsigned rh = f2tf(vre); unsigned rl = f2tf(vre - __uint_as_float(rh));
        unsigned ih = f2tf(vim); unsigned il = f2tf(vim - __uint_as_float(ih));
        int ks = o >> 3, k8 = o & 7, mm = kp & 15;
        int lane = (mm & 7)*4 + (k8 & 3);
        int reg  = (mm >> 3) + 2*(k8 >> 2);
        int idx = i*16384 + ((kp >> 4)*16 + ks)*128 + lane*4 + reg;
        g_A1f[idx]           = rh;
        g_A1f[A1F_P   + idx] = rl;
        g_A1f[2*A1F_P + idx] = ih;
        g_A1f[3*A1F_P + idx] = il;
        g_A1f[4*A1F_P + idx] = ih ^ 0x80000000u;
        g_A1f[5*A1F_P + idx] = il ^ 0x80000000u;
        float t = ty[o];
        float e = expf(wr * t);
        float sn, cs; sincosf(wi * t, &sn, &cs);
        g_E1[ikp*NY + o] = make_float2(e*cs, e*sn);
    } else {
        int ikq = blk - CI*CO*M1;
        float wr = wp2_re[ikq], wi = wp2_im[ikq];
        float d = tx[1] - tx[0];
        float invnd = 1.0f / ((float)NX * d);
        float k = (o < NX/2) ? (float)o : (float)(o - NX);
        float lam = TWO_PI_F * k * invnd;
        float a = -wr, b = lam - wi;
        float inv = 1.0f / (a*a + b*b);
        g_A2[ikq*NX + o] = make_float2(a*inv, -b*inv);
        float t = tx[o];
        float e = expf(wr * t);
        float sn, cs; sincosf(wi * t, &sn, &cs);
        g_E2[ikq*NX + o] = make_float2(e*cs, e*sn);
    }
}

// ---------------- 128-pt radix-2 DIT (row FFT) -------------------------------
template<int INV>
__device__ __forceinline__ void fft64th(float2* s, int tt, const float2* tws) {
    #pragma unroll
    for (int stage = 1; stage <= 7; stage++) {
        __syncthreads();
        int half = 1 << (stage - 1);
        int p  = tt & (half - 1);
        int i0 = ((tt >> (stage - 1)) << stage) + p;
        int i1 = i0 + half;
        float2 w = tws[p << (7 - stage)];
        float2 u = s[i0];
        float2 v = twmul<INV>(s[i1], w);
        s[i0] = make_float2(u.x + v.x, u.y + v.y);
        s[i1] = make_float2(u.x - v.x, u.y - v.y);
    }
}

// forward FFT of real rows (launch 1)
__global__ void k_fft_rows_f(const float* __restrict__ x) {
    __shared__ float2 s[2][NX];
    __shared__ float2 tws[64];
    int t = threadIdx.x, r = t >> 6, tt = t & 63;
    make_tws(tws, t);
    size_t row = (size_t)blockIdx.x * 2 + r;
    const float* xr = x + row * NX;
    s[r][tt]      = make_float2(xr[__brev(tt)      >> 25], 0.f);
    s[r][tt + 64] = make_float2(xr[__brev(tt + 64) >> 25], 0.f);
    fft64th<0>(s[r], tt, tws);
    float2* o = g_tmp + row * NX;
    o[tt] = s[r][tt]; o[tt + 64] = s[r][tt + 64];
}

// ---------------- fused-pair (radix-4 style) column FFT ----------------------
template<int INV>
__device__ __forceinline__ void fft_col4(float2 (*tile)[17], int tg, int tx, const float2* tws) {
    #pragma unroll
    for (int s = 1; s <= 5; s += 2) {
        __syncthreads();
        int h = 1 << (s - 1);
        #pragma unroll
        for (int m = 0; m < 4; m++) {
            int j = tg + 8 * m;
            int p = j & (h - 1);
            int base = ((j >> (s - 1)) << (s + 1)) + p;
            float2 w1  = tws[p << (7 - s)];
            float2 w2  = tws[p << (6 - s)];
            float2 w2b = tws[(p + h) << (6 - s)];
            float2 a = tile[base][tx],       bb = tile[base + h][tx];
            float2 c = tile[base + 2*h][tx], dd = tile[base + 3*h][tx];
            float2 vb = twmul<INV>(bb, w1);
            float2 vd = twmul<INV>(dd, w1);
            float2 a1 = make_float2(a.x + vb.x, a.y + vb.y);
            float2 b1 = make_float2(a.x - vb.x, a.y - vb.y);
            float2 c1 = make_float2(c.x + vd.x, c.y + vd.y);
            float2 d1 = make_float2(c.x - vd.x, c.y - vd.y);
            float2 vc = twmul<INV>(c1, w2);
            float2 ve = twmul<INV>(d1, w2b);
            tile[base][tx]       = make_float2(a1.x + vc.x, a1.y + vc.y);
            tile[base + 2*h][tx] = make_float2(a1.x - vc.x, a1.y - vc.y);
            tile[base + h][tx]   = make_float2(b1.x + ve.x, b1.y + ve.y);
            tile[base + 3*h][tx] = make_float2(b1.x - ve.x, b1.y - ve.y);
        }
    }
    __syncthreads();
    #pragma unroll
    for (int m = 0; m < 8; m++) {
        int j = tg + 8 * m;
        float2 w = tws[j];
        float2 u = tile[j][tx];
        float2 v = twmul<INV>(tile[j + 64][tx], w);
        tile[j][tx]      = make_float2(u.x + v.x, u.y + v.y);
        tile[j + 64][tx] = make_float2(u.x - v.x, u.y - v.y);
    }
}

// forward columns (launch 2): g_tmp -> g_alpha
__global__ void k_fft_cols_f() {
    __shared__ float2 tile[NY][17];
    __shared__ float2 tws[64];
    int t = threadIdx.x;
    make_tws(tws, t);
    int blk = blockIdx.x;
    int xt = blk & 7, img = blk >> 3;
    int x0 = xt * 16;
    int tg = t >> 4, tx = t & 15;
    const float2* base = g_tmp + (size_t)img * NY * NX + x0;
    #pragma unroll
    for (int c = 0; c < 16; c++) {
        int y = c * 8 + tg;
        tile[__brev(y) >> 25][tx] = base[(size_t)y * NX + tx];
    }
    fft_col4<0>(tile, tg, tx, tws);
    __syncthreads();
    float2* ob = g_alpha + (size_t)img * NY * NX + x0;
    #pragma unroll
    for (int c = 0; c < 16; c++) {
        int y = c * 8 + tg;
        ob[(size_t)y * NX + tx] = tile[y][tx];
    }
}

// ---------------- S1 via tf32 mma, A frags from global (launch 3) ------------
// x-quarter blocks: B planes 64 KB smem -> 3 blocks/SM. 8 warps = 2 mt x 4 nt.
#define S1M_SMEM (4*4096*4)
extern __shared__ float2 dynsm[];
__global__ void __launch_bounds__(256, 3) k_S1() {
    unsigned* Bp = (unsigned*)dynsm;   // 4 planes x 4096: Brh, Brl, Bih, Bil
    int blk = blockIdx.x;
    int xq = blk & 3;
    int bi = blk >> 2;
    int i  = bi & 31;
    int x0 = xq * 32;
    int t  = threadIdx.x;
    const float2* A = g_alpha + (size_t)bi * NY * NX + x0;
    for (int e = t; e < 128*32; e += 256) {
        int o = e >> 5, x = e & 31;
        float2 v = A[(size_t)o * NX + x];
        unsigned rh = f2tf(v.x); float rlo = v.x - __uint_as_float(rh);
        unsigned ih = f2tf(v.y); float ilo = v.y - __uint_as_float(ih);
        int nt = x >> 3, n = x & 7, ks = o >> 3, k = o & 7;
        int idx = ((nt*16 + ks)*32 + (n*4 + (k & 3)))*2 + (k >> 2);
        Bp[idx]         = rh;
        Bp[4096  + idx] = f2tf(rlo);
        Bp[8192  + idx] = ih;
        Bp[12288 + idx] = f2tf(ilo);
    }
    __syncthreads();
    int w = t >> 5, l = t & 31;
    int mt = w & 1;
    int nt = w >> 1;
    const unsigned* A1f = g_A1f + (size_t)i * 16384;
    #pragma unroll 1
    for (int c = 0; c < 4; c++) {
        float cre[4] = {0.f,0.f,0.f,0.f};
        float cim[4] = {0.f,0.f,0.f,0.f};
        #pragma unroll 2
        for (int ks = 0; ks < 16; ks++) {
            int ab = ((c*2 + mt)*16 + ks)*128 + l*4;
            unsigned arh[4], arl[4], aih[4], ail[4], nih[4], nil[4];
            *(uint4*)arh = *(const uint4*)&A1f[ab];
            *(uint4*)arl = *(const uint4*)&A1f[A1F_P   + ab];
            *(uint4*)aih = *(const uint4*)&A1f[2*A1F_P + ab];
            *(uint4*)ail = *(const uint4*)&A1f[3*A1F_P + ab];
            *(uint4*)nih = *(const uint4*)&A1f[4*A1F_P + ab];
            *(uint4*)nil = *(const uint4*)&A1f[5*A1F_P + ab];
            int bb = ((nt*16 + ks)*32 + l)*2;
            unsigned brh[2], brl[2], bih[2], bil[2];
            *(uint2*)brh = *(const uint2*)&Bp[bb];
            *(uint2*)brl = *(const uint2*)&Bp[4096  + bb];
            *(uint2*)bih = *(const uint2*)&Bp[8192  + bb];
            *(uint2*)bil = *(const uint2*)&Bp[12288 + bb];
            mma_tf32(cre, arh, brh);
            mma_tf32(cre, arl, brh);
            mma_tf32(cre, arh, brl);
            mma_tf32(cre, nih, bih);
            mma_tf32(cre, nil, bih);
            mma_tf32(cre, nih, bil);
            mma_tf32(cim, arh, bih);
            mma_tf32(cim, arl, bih);
            mma_tf32(cim, arh, bil);
            mma_tf32(cim, aih, brh);
            mma_tf32(cim, ail, brh);
            mma_tf32(cim, aih, brl);
        }
        int row0 = c*32 + mt*16 + (l >> 2);
        int col  = x0 + nt*8 + (l & 3)*2;
        float4 v0 = make_float4(cre[0], cim[0], cre[1], cim[1]);
        float4 v1 = make_float4(cre[2], cim[2], cre[3], cim[3]);
        *(float4*)(g_S1 + ((size_t)bi*CO*M1 + row0) * NX + col)     = v0;
        *(float4*)(g_S1 + ((size_t)bi*CO*M1 + row0 + 8) * NX + col) = v1;
    }
}

// ---------------- Hsum with inline A1/A2 (launch 4) --------------------------
__global__ void k_hsum(const float* __restrict__ wp1_re, const float* __restrict__ wp1_im,
                       const float* __restrict__ wp2_re, const float* __restrict__ wp2_im,
                       const float* __restrict__ ty, const float* __restrict__ tx,
                       const float* __restrict__ wr_re, const float* __restrict__ wr_im) {
    int ik = blockIdx.x;
    int t  = threadIdx.x;
    __shared__ float2 wrS[M1*M2];
    __shared__ float2 A1S[M1][NY];
    __shared__ float2 U[M2][NY];
    if (t < M1*M2) wrS[t] = make_float2(wr_re[ik*M1*M2 + t], wr_im[ik*M1*M2 + t]);
    float kf = (t < NY/2) ? (float)t : (float)(t - NY);
    {
        float d = ty[1] - ty[0];
        float invnd = 1.0f / ((float)NY * d);
        float lam = TWO_PI_F * kf * invnd;
        #pragma unroll
        for (int p = 0; p < M1; p++) {
            float wr = wp1_re[ik*M1 + p], wi = wp1_im[ik*M1 + p];
            float a = -wr, b = lam - wi;
            float inv = 1.0f / (a*a + b*b);
            A1S[p][t] = make_float2(a*inv, -b*inv);
        }
    }
    float2 a2[M2];
    {
        float d = tx[1] - tx[0];
        float invnd = 1.0f / ((float)NX * d);
        float lam = TWO_PI_F * kf * invnd;
        #pragma unroll
        for (int q = 0; q < M2; q++) {
            float wr = wp2_re[ik*M2 + q], wi = wp2_im[ik*M2 + q];
            float a = -wr, b = lam - wi;
            float inv = 1.0f / (a*a + b*b);
            a2[q] = make_float2(a*inv, -b*inv);
        }
    }
    __syncthreads();
    #pragma unroll
    for (int q = 0; q < M2; q++) {
        float2 acc = make_float2(0.f, 0.f);
        #pragma unroll
        for (int p = 0; p < M1; p++) acc = cfma(wrS[p*M2 + q], A1S[p][t], acc);
        U[q][t] = acc;
    }
    __syncthreads();
    float2* H = g_H + (size_t)ik * NY * NX;
    for (int o = 0; o < NY; o++) {
        float2 acc = make_float2(0.f, 0.f);
        #pragma unroll
        for (int q = 0; q < M2; q++) acc = cfma(U[q][o], a2[q], acc);
        __stcs(&H[o*NX + t], acc);
    }
}

// ---------------- res2 (launch 5) --------------------------------------------
__global__ void k_res2(const float* __restrict__ wr_re, const float* __restrict__ wr_im) {
    int bk = blockIdx.x;
    int b = bk >> 5, k = bk & 31;
    int t = threadIdx.x;
    __shared__ float2 wrS[CI][M1*M2];
    for (int idx = t; idx < CI*M1*M2; idx += 128) {
        int i = idx / (M1*M2), pq = idx % (M1*M2);
        wrS[i][pq] = make_float2(wr_re[(i*CO + k)*M1*M2 + pq], wr_im[(i*CO + k)*M1*M2 + pq]);
    }
    __syncthreads();
    float2 acc[M1*M2];
    #pragma unroll
    for (int j = 0; j < M1*M2; j++) acc[j] = make_float2(0.f, 0.f);
    for (int i = 0; i < CI; i++) {
        float2 s1[M1], a2[M2];
        #pragma unroll
        for (int p = 0; p < M1; p++)
            s1[p] = g_S1[((size_t)(b*CI + i)*CO*M1 + k*M1 + p)*NX + t];
        #pragma unroll
        for (int q = 0; q < M2; q++)
            a2[q] = g_A2[((size_t)(i*CO + k)*M2 + q)*NX + t];
        #pragma unroll
        for (int p = 0; p < M1; p++)
            #pragma unroll
            for (int q = 0; q < M2; q++) {
                float2 wa = cmul(wrS[i][p*M2 + q], s1[p]);
                acc[p*M2 + q] = cfma(wa, a2[q], acc[p*M2 + q]);
            }
    }
    #pragma unroll
    for (int j = 0; j < M1*M2; j++)
        #pragma unroll
        for (int off = 16; off; off >>= 1) {
            acc[j].x += __shfl_down_sync(0xffffffffu, acc[j].x, off);
            acc[j].y += __shfl_down_sync(0xffffffffu, acc[j].y, off);
        }
    __shared__ float2 red[4][M1*M2];
    int w = t >> 5, lane = t & 31;
    if (lane == 0) {
        #pragma unroll
        for (int j = 0; j < M1*M2; j++) red[w][j] = acc[j];
    }
    __syncthreads();
    if (t < M1*M2) {
        float2 s = red[0][t];
        #pragma unroll
        for (int w2 = 1; w2 < 4; w2++) { s.x += red[w2][t].x; s.y += red[w2][t].y; }
        g_res2[bk*M1*M2 + t] = s;
    }
}

// ---------------- res1 + inverse row FFT (fused pairs), k-tile 2 (launch 6) --
__global__ void __launch_bounds__(128, 5) k_res1f() {
    __shared__ float2 rows[16][129];
    __shared__ float2 tws[64];
    int o  = blockIdx.x & 127;
    int k0 = (blockIdx.x >> 7) * 2;
    int x  = threadIdx.x;
    make_tws(tws, x);
    const ull* alphaU = (const ull*)g_alpha;
    ull acc[2][B];
    #pragma unroll
    for (int kk = 0; kk < 2; kk++)
        #pragma unroll
        for (int b = 0; b < B; b++) acc[kk][b] = pack2(0.f, 0.f);

    for (int i = 0; i < CI; i++) {
        float2 hc[2];
        #pragma unroll
        for (int kk = 0; kk < 2; kk++)
            hc[kk] = __ldcs(&g_H[((size_t)(i*CO + k0 + kk) * NY + o) * NX + x]);
        ull ac[8];
        #pragma unroll
        for (int b = 0; b < B; b++)
            ac[b] = alphaU[((size_t)(b*CI + i) * NY + o) * NX + x];
        ull hxx[2], hpm[2];
        #pragma unroll
        for (int kk = 0; kk < 2; kk++) {
            hxx[kk] = pack2(hc[kk].x,  hc[kk].x);
            hpm[kk] = pack2(-hc[kk].y, hc[kk].y);
        }
        #pragma unroll
        for (int b = 0; b < B; b++) {
            ull au = ac[b];
            ull as = swap2(au);
            #pragma unroll
            for (int kk = 0; kk < 2; kk++) {
                acc[kk][b] = fma2(au, hxx[kk], acc[kk][b]);
                acc[kk][b] = fma2(as, hpm[kk], acc[kk][b]);
            }
        }
    }
    int xr = __brev(x) >> 25;
    #pragma unroll
    for (int kk = 0; kk < 2; kk++)
        #pragma unroll
        for (int b = 0; b < B; b++)
            rows[kk*8 + b][xr] = unpack2(acc[kk][b]);
    __syncthreads();
    #pragma unroll
    for (int s = 1; s <= 5; s += 2) {
        int h = 1 << (s - 1);
        #pragma unroll
        for (int m = 0; m < 4; m++) {
            int l = x + 128 * m;
            int r = l >> 5, j = l & 31;
            int p = j & (h - 1);
            int base = ((j >> (s - 1)) << (s + 1)) + p;
            float2 w1  = tws[p << (7 - s)];
            float2 w2  = tws[p << (6 - s)];
            float2 w2b = tws[(p + h) << (6 - s)];
            float2 a = rows[r][base],       bb = rows[r][base + h];
            float2 c = rows[r][base + 2*h], dd = rows[r][base + 3*h];
            float2 vb = twmul<1>(bb, w1);
            float2 vd = twmul<1>(dd, w1);
            float2 a1 = make_float2(a.x + vb.x, a.y + vb.y);
            float2 b1 = make_float2(a.x - vb.x, a.y - vb.y);
            float2 c1 = make_float2(c.x + vd.x, c.y + vd.y);
            float2 d1 = make_float2(c.x - vd.x, c.y - vd.y);
            float2 vc = twmul<1>(c1, w2);
            float2 ve = twmul<1>(d1, w2b);
            rows[r][base]       = make_float2(a1.x + vc.x, a1.y + vc.y);
            rows[r][base + 2*h] = make_float2(a1.x - vc.x, a1.y - vc.y);
            rows[r][base + h]   = make_float2(b1.x + ve.x, b1.y + ve.y);
            rows[r][base + 3*h] = make_float2(b1.x - ve.x, b1.y - ve.y);
        }
        __syncthreads();
    }
    #pragma unroll
    for (int m = 0; m < 8; m++) {
        int l = x + 128 * m;
        int r = l >> 6, j = l & 63;
        float2 w = tws[j];
        float2 u = rows[r][j];
        float2 v = twmul<1>(rows[r][j + 64], w);
        rows[r][j]      = make_float2(u.x + v.x, u.y + v.y);
        rows[r][j + 64] = make_float2(u.x - v.x, u.y - v.y);
    }
    __syncthreads();
    #pragma unroll
    for (int kk = 0; kk < 2; kk++)
        #pragma unroll
        for (int b = 0; b < B; b++)
            g_tmp[(((size_t)(b*CO + k0 + kk)) * NY + o) * NX + x] = rows[kk*8 + b][x];
}

// ---------------- inverse columns, fused pairs (launch 7) --------------------
__global__ void k_ifft_cols_r(float* __restrict__ out) {
    __shared__ float2 tile[NY][17];
    __shared__ float2 tws[64];
    int t = threadIdx.x;
    make_tws(tws, t);
    int blk = blockIdx.x;
    int xt = blk & 7, img = blk >> 3;
    int x0 = xt * 16;
    int tg = t >> 4, tx = t & 15;
    const float2* base = g_tmp + (size_t)img * NY * NX + x0;
    #pragma unroll
    for (int c = 0; c < 16; c++) {
        int y = c * 8 + tg;
        tile[__brev(y) >> 25][tx] = base[(size_t)y * NX + tx];
    }
    fft_col4<1>(tile, tg, tx, tws);
    __syncthreads();
    const float INV = 1.0f / (float)(NY * NX);
    float* ob = out + (size_t)img * NY * NX + x0;
    #pragma unroll
    for (int c = 0; c < 16; c++) {
        int y = c * 8 + tg;
        ob[(size_t)y * NX + tx] = tile[y][tx].x * INV;
    }
}

// ---------------- x2 with fused G (launch 8) ---------------------------------
#define X2_E1   (128*64)
#define X2_R2   (CI*M1*M2)
#define X2_GS   (16*66)
#define X2_ES   (16*129)
#define X2_SMEM ((X2_E1 + X2_R2 + X2_GS + X2_ES) * sizeof(float2))
__global__ void __launch_bounds__(256) k_x2(float* __restrict__ out) {
    float2* e1S = dynsm;
    float2* r2S = e1S + X2_E1;
    float2* Gs  = r2S + X2_R2;
    float2* Es  = Gs + X2_GS;
    int blk = blockIdx.x;
    int zh  = blk & 1;
    int bk  = blk >> 1;
    int b = bk >> 5, k = bk & 31;
    int z0 = zh * 64;
    int t = threadIdx.x;
    int u = t >> 5, v = t & 31;
    for (int l = t; l < X2_E1; l += 256) {
        int cp = l >> 6, zz = l & 63;
        e1S[l] = g_E1[(((cp >> 2)*CO + k)*M1 + (cp & 3))*NY + z0 + zz];
    }
    for (int l = t; l < X2_R2; l += 256)
        r2S[l] = g_res2[(b*CO + (l/20))*20 + (l%20)];
    ull acc[8][4];
    #pragma unroll
    for (int j = 0; j < 8; j++)
        #pragma unroll
        for (int m = 0; m < 4; m++) acc[j][m] = pack2(0.f, 0.f);
    for (int k0 = 0; k0 < CI*M2; k0 += 16) {
        __syncthreads();
        for (int l = t; l < 16*64; l += 256) {
            int r = l >> 6, zz = l & 63;
            int cq = k0 + r; int c = cq / M2, q = cq % M2;
            float2 g = make_float2(0.f, 0.f);
            #pragma unroll
            for (int p = 0; p < M1; p++)
                g = cfma(r2S[c*20 + p*M2 + q], e1S[(c*4 + p)*64 + zz], g);
            Gs[r*66 + zz] = g;
        }
        for (int l = t; l < 16*128; l += 256) {
            int r = l >> 7, xx = l & 127;
            int cq = k0 + r; int c = cq / M2, q = cq % M2;
            Es[r*129 + xx] = g_E2[((size_t)(c*CO + k)*M2 + q)*NX + xx];
        }
        __syncthreads();
        #pragma unroll
        for (int kk = 0; kk < 16; kk++) {
            ulonglong2 gp[4];
            const ulonglong2* gq = (const ulonglong2*)&Gs[kk*66 + u*8];
            #pragma unroll
            for (int jp = 0; jp < 4; jp++) gp[jp] = gq[jp];
            #pragma unroll
            for (int m = 0; m < 4; m++) {
                ull e = *(const ull*)&Es[kk*129 + v + 32*m];
                #pragma unroll
                for (int jp = 0; jp < 4; jp++) {
                    acc[2*jp  ][m] = fma2(gp[jp].x, e, acc[2*jp  ][m]);
                    acc[2*jp+1][m] = fma2(gp[jp].y, e, acc[2*jp+1][m]);
                }
            }
        }
    }
    const float INV = 1.0f / (float)(NY * NX);
    float* ob = out + (size_t)(b*CO + k) * NY * NX;
    #pragma unroll
    for (int j = 0; j < 8; j++) {
        int z = z0 + u*8 + j;
        #pragma unroll
        for (int m = 0; m < 4; m++) {
            float2 r = unpack2(acc[j][m]);
            ob[(size_t)z * NX + v + 32*m] += (r.x - r.y) * INV;
        }
    }
}

// ---------------------------------------------------------------------------
extern "C" void kernel_launch(void* const* d_in, const int* in_sizes, int n_in,
                              void* d_out, int out_size) {
    const float* x      = (const float*)d_in[0];
    const float* wp1_re = (const float*)d_in[1];
    const float* wp1_im = (const float*)d_in[2];
    const float* wp2_re = (const float*)d_in[3];
    const float* wp2_im = (const float*)d_in[4];
    const float* wr_re  = (const float*)d_in[5];
    const float* wr_im  = (const float*)d_in[6];
    const float* ty     = (const float*)d_in[7];
    const float* tx     = (const float*)d_in[8];
    float* out = (float*)d_out;

    cudaFuncSetAttribute(k_S1, cudaFuncAttributeMaxDynamicSharedMemorySize, S1M_SMEM);
    cudaFuncSetAttribute(k_x2, cudaFuncAttributeMaxDynamicSharedMemorySize, (int)X2_SMEM);

    k_fac         <<<CI*CO*(M1+M2), 128>>>(wp1_re, wp1_im, wp2_re, wp2_im, ty, tx);       // 0
    k_fft_rows_f  <<<B*CI*NY/2, 128>>>(x);                                                // 1
    k_fft_cols_f  <<<B*CI*8, 128>>>();                                                    // 2
    k_S1          <<<B*CI*4, 256, S1M_SMEM>>>();                                          // 3 (profiled)
    k_hsum        <<<CI*CO, 128>>>(wp1_re, wp1_im, wp2_re, wp2_im, ty, tx, wr_re, wr_im); // 4
    k_res2        <<<B*CO, 128>>>(wr_re, wr_im);                                          // 5
    k_res1f       <<<16*NY, 128>>>();                                                     // 6
    k_ifft_cols_r <<<B*CO*8, 128>>>(out);                                                 // 7
    k_x2          <<<B*CO*2, 256, X2_SMEM>>>(out);                                        // 8
}